// round 16
// baseline (speedup 1.0000x reference)
#include <cuda_runtime.h>
#include <cstdint>

// ZoeDepth metric depth head — fused, tiled 16x8 CTA, smem-staged bilinear,
// 1024-thread CTA (64-reg cap -> 32 warps/SM). Phases re-partitioned:
// gather/attractor 8 thr/px, GEMM1 16x32 warp tiles (32 warps), GEMM2 16 warps,
// sort 2 thr/px sign-encoded bitonic (R15-proven).

namespace {
constexpr int Hc = 192, Wc = 192, SHc = 96, SWc = 96, Cc = 128, NB = 64, NA = 16;
constexpr int NTHR = 1024;
constexpr int TW = 16, TH = 8;                 // 128 px per tile
constexpr float ALPHAc = 300.0f;
constexpr int LDP2 = 136;                      // paired V/W row stride
constexpr int PESTR = 72;                      // pe/pb smem channel stride (60 used)
constexpr int ARRSTR = 136;                    // sort staging stride

// smem layout (floats)
constexpr int OFF_PE  = 0;                       // 128*72 ; reused for pb (64*72)
constexpr int OFF_V   = OFF_PE + 128 * PESTR;    // 128*136 ; reused as arr_s
constexpr int OFF_W1  = OFF_V + 128 * LDP2;      // 128*136 ; reused as h tile
constexpr int OFF_W2E = OFF_W1 + 128 * LDP2;     // 16*136
constexpr int OFF_B1S = OFF_W2E + 16 * LDP2;     // 128
constexpr int OFF_B2S = OFF_B1S + 128;           // 16
constexpr int OFF_ATT = OFF_B2S + 16;            // 128*16 (16B aligned)
constexpr int SMEM_FLOATS = OFF_ATT + 128 * 16;
constexpr int SMEM_BYTES  = SMEM_FLOATS * 4;     // 193600 B

__device__ __forceinline__ int pslot(int c) {
    return ((c >> 3) << 3) + ((c & 3) << 1) + ((c >> 2) & 1);
}
__device__ __forceinline__ float rna_tf32(float x) {
    float r; asm("cvt.rna.tf32.f32 %0, %1;" : "=f"(r) : "f"(x)); return r;
}
__device__ __forceinline__ float rcpa(float x) {
    float r; asm("rcp.approx.f32 %0, %1;" : "=f"(r) : "f"(x)); return r;
}
__device__ __forceinline__ unsigned long long pack2(float lo, float hi) {
    unsigned long long r;
    asm("mov.b64 %0, {%1, %2};" : "=l"(r) : "f"(lo), "f"(hi));
    return r;
}
__device__ __forceinline__ void unpack2(unsigned long long v, float& lo, float& hi) {
    asm("mov.b64 {%0, %1}, %2;" : "=f"(lo), "=f"(hi) : "l"(v));
}
__device__ __forceinline__ unsigned long long fma2(unsigned long long a,
                                                   unsigned long long b,
                                                   unsigned long long c) {
    unsigned long long d;
    asm("fma.rn.f32x2 %0, %1, %2, %3;" : "=l"(d) : "l"(a), "l"(b), "l"(c));
    return d;
}
__device__ __forceinline__ void mma_tf32(float* d,
                                         uint32_t a0, uint32_t a1, uint32_t a2, uint32_t a3,
                                         uint32_t b0, uint32_t b1) {
    asm volatile("mma.sync.aligned.m16n8k8.row.col.f32.tf32.tf32.f32 "
                 "{%0,%1,%2,%3}, {%4,%5,%6,%7}, {%8,%9}, {%0,%1,%2,%3};"
                 : "+f"(d[0]), "+f"(d[1]), "+f"(d[2]), "+f"(d[3])
                 : "r"(a0), "r"(a1), "r"(a2), "r"(a3), "r"(b0), "r"(b1));
}
__device__ __forceinline__ uint32_t fu(float x) { return __float_as_uint(x); }
} // namespace

__global__ __launch_bounds__(NTHR, 1)
void zoe_head_tile_kernel(const float* __restrict__ x,
                          const float* __restrict__ prev_bin,
                          const float* __restrict__ pe,
                          const float* __restrict__ w1,
                          const float* __restrict__ b1,
                          const float* __restrict__ w2,
                          const float* __restrict__ b2,
                          float* __restrict__ out,
                          long long half_out)
{
    extern __shared__ float smem[];
    float* peS  = smem + OFF_PE;     // reused for pb staging
    float* vS   = smem + OFF_V;      // reused as sort staging
    float* w1S  = smem + OFF_W1;     // reused as h tile
    float* w2eS = smem + OFF_W2E;
    float* b1S  = smem + OFF_B1S;
    float* b2S  = smem + OFF_B2S;
    float* attS = smem + OFF_ATT;

    const int t = threadIdx.x;
    const int wid = t >> 5, lid = t & 31;
    const int g = lid >> 2, tig = lid & 3;
    const int HW = Hc * Wc, SHW = SHc * SWc;

    // ---- tile coords ----
    const int bx = blockIdx.x;
    const int tX = (bx % 12) * TW;
    const int tY = ((bx / 12) % 24) * TH;
    const int bI = bx / 288;
    const float fscale = (float)(SHc - 1) / (float)(Hc - 1);
    const int ybase = (int)((float)tY * fscale);
    const int xbase = (int)((float)tX * fscale);

    // ---- stage W1 / W2even / biases into paired tf32 layout ----
    {
        const float4* w1v = (const float4*)w1;
#pragma unroll
        for (int i = 0; i < 2; i++) {
            int idx8 = t + i * NTHR;          // 0..2047
            int o = idx8 >> 4, g8 = idx8 & 15;
            float4 lo = w1v[o * 32 + g8 * 2];
            float4 hi = w1v[o * 32 + g8 * 2 + 1];
            float* dst = &w1S[o * LDP2 + g8 * 8];
            *(float2*)&dst[0] = make_float2(rna_tf32(lo.x), rna_tf32(hi.x));
            *(float2*)&dst[2] = make_float2(rna_tf32(lo.y), rna_tf32(hi.y));
            *(float2*)&dst[4] = make_float2(rna_tf32(lo.z), rna_tf32(hi.z));
            *(float2*)&dst[6] = make_float2(rna_tf32(lo.w), rna_tf32(hi.w));
        }
        if (t < 256) {
            int o = t >> 4, g8 = t & 15;
            const float4* w2v = (const float4*)w2;
            float4 lo = w2v[(2 * o) * 32 + g8 * 2];
            float4 hi = w2v[(2 * o) * 32 + g8 * 2 + 1];
            float* dst = &w2eS[o * LDP2 + g8 * 8];
            *(float2*)&dst[0] = make_float2(rna_tf32(lo.x), rna_tf32(hi.x));
            *(float2*)&dst[2] = make_float2(rna_tf32(lo.y), rna_tf32(hi.y));
            *(float2*)&dst[4] = make_float2(rna_tf32(lo.z), rna_tf32(hi.z));
            *(float2*)&dst[6] = make_float2(rna_tf32(lo.w), rna_tf32(hi.w));
        }
        if (t < Cc) b1S[t] = b1[t];
        if (t < NA) b2S[t] = b2[2 * t];
    }

    // ---- stage pe source tile: 128 ch x 6 rows x 10 cols ----
    {
        const float* peb = pe + (long long)bI * Cc * SHW;
#pragma unroll
        for (int i = 0; i < 8; i++) {
            int idx = t + i * NTHR;            // 0..8191, need 7680
            if (idx < 7680) {
                int c = idx / 60, r = idx - c * 60;
                int ly = r / 10, lx = r - ly * 10;
                int sy = min(ybase + ly, SHc - 1);
                int sx = min(xbase + lx, SWc - 1);
                peS[c * PESTR + r] = __ldg(peb + (long long)c * SHW + sy * SWc + sx);
            }
        }
    }

    // ---- per-pixel bilinear coords (8 threads per pixel) ----
    const int pxl = t >> 3;                    // 0..127
    const int q8  = t & 7;
    const int q4  = q8 & 3;
    const int hb  = q8 >> 2;                   // channel-half bit
    const int py = pxl >> 4, px = pxl & 15;
    const int yy = tY + py, xx = tX + px;
    const int rem = yy * Wc + xx;
    const float fy = yy * fscale, fx = xx * fscale;
    const int y0 = (int)fy, x0 = (int)fx;
    const int y1 = min(y0 + 1, SHc - 1), x1 = min(x0 + 1, SWc - 1);
    const float wy = fy - (float)y0, wx = fx - (float)x0;
    const float w00 = (1.f - wy) * (1.f - wx), w01 = (1.f - wy) * wx;
    const float w10 = wy * (1.f - wx),          w11 = wy * wx;
    const int o00 = (y0 - ybase) * 10 + (x0 - xbase);
    const int o01 = (y0 - ybase) * 10 + (x1 - xbase);
    const int o10 = (y1 - ybase) * 10 + (x0 - xbase);
    const int o11 = (y1 - ybase) * 10 + (x1 - xbase);

    __syncthreads();   // weights + pe tile staged

    // ---- build V tile: v = x + bilinear(peS), rna->tf32, paired layout ----
    // thread handles m in [hb*8, hb*8+8), channel pair (8m+q4, 8m+q4+4)
    {
        const float* xb = x + (long long)bI * Cc * HW + rem;
        float* vrow = vS + pxl * LDP2;
#pragma unroll
        for (int j = 0; j < 8; j++) {
            const int m = hb * 8 + j;
            const int c0 = 8 * m + q4;
            const float* p0 = peS + c0 * PESTR;
            const float* p1 = p0 + 4 * PESTR;
            float v0 = w00 * p0[o00] + w01 * p0[o01] + w10 * p0[o10] + w11 * p0[o11]
                     + __ldg(xb + (long long)c0 * HW);
            float v1 = w00 * p1[o00] + w01 * p1[o01] + w10 * p1[o10] + w11 * p1[o11]
                     + __ldg(xb + (long long)(c0 + 4) * HW);
            *(float2*)&vrow[m * 8 + q4 * 2] = make_float2(rna_tf32(v0), rna_tf32(v1));
        }
    }
    __syncthreads();   // V ready; peS dead

    // ---- GEMM1: 32 warps = 8x4, warp tile 16x32 ----
    const int rg = wid >> 2, cgw = wid & 3;
    const int r0 = rg * 16, c0 = cgw * 32;
    float acc[4][4];
#pragma unroll
    for (int ct = 0; ct < 4; ct++)
#pragma unroll
        for (int qq = 0; qq < 4; qq++) acc[ct][qq] = 0.f;

#pragma unroll 4
    for (int k = 0; k < 16; k++) {
        const int kb = k * 8 + 2 * tig;
        float2 A0 = *(const float2*)&vS[(r0 + g) * LDP2 + kb];
        float2 A1 = *(const float2*)&vS[(r0 + g + 8) * LDP2 + kb];
#pragma unroll
        for (int ct = 0; ct < 4; ct++) {
            float2 B = *(const float2*)&w1S[(c0 + ct * 8 + g) * LDP2 + kb];
            mma_tf32(acc[ct], fu(A0.x), fu(A1.x), fu(A0.y), fu(A1.y), fu(B.x), fu(B.y));
        }
    }

    // ---- stage prev_bin tile into peS region (overlaps other warps' MMA) ----
    {
        const float* pbb = prev_bin + (long long)bI * NB * SHW;
#pragma unroll
        for (int i = 0; i < 4; i++) {
            int idx = t + i * NTHR;            // 0..4095, need 3840
            if (idx < 3840) {
                int c = idx / 60, r = idx - c * 60;
                int ly = r / 10, lx = r - ly * 10;
                int sy = min(ybase + ly, SHc - 1);
                int sx = min(xbase + lx, SWc - 1);
                peS[c * PESTR + r] = __ldg(pbb + (long long)c * SHW + sy * SWc + sx);
            }
        }
    }
    __syncthreads();   // GEMM1 done everywhere -> w1S overwritable; pbS ready

    // ---- epilogue 1: h = rna(relu(D1+b1)) -> h tile (w1S region, paired) ----
    {
        float* hS = w1S;
        const int ra = (r0 + g) * LDP2;
        const int rb = ra + 8 * LDP2;
#pragma unroll
        for (int ct = 0; ct < 4; ct++) {
            const int c = c0 + ct * 8 + 2 * tig;
            const float bb0 = b1S[c], bb1 = b1S[c + 1];
            const int s0 = pslot(c), s1 = pslot(c + 1);
            hS[ra + s0] = rna_tf32(fmaxf(acc[ct][0] + bb0, 0.f));
            hS[ra + s1] = rna_tf32(fmaxf(acc[ct][1] + bb1, 0.f));
            hS[rb + s0] = rna_tf32(fmaxf(acc[ct][2] + bb0, 0.f));
            hS[rb + s1] = rna_tf32(fmaxf(acc[ct][3] + bb1, 0.f));
        }
    }
    __syncthreads();

    // ---- GEMM2 (warps 0..15): att[16 rows][8 cols] ----
    if (wid < 16) {
        const float* hS = w1S;
        const int rg2 = wid >> 1, ch2 = wid & 1;
        const int rA0 = (rg2 * 16 + g) * LDP2;
        const int rA1 = rA0 + 8 * LDP2;
        float acc2[4] = {0.f, 0.f, 0.f, 0.f};
#pragma unroll
        for (int k = 0; k < 16; k++) {
            const int kb = k * 8 + 2 * tig;
            float2 HA0 = *(const float2*)&hS[rA0 + kb];
            float2 HA1 = *(const float2*)&hS[rA1 + kb];
            float2 B = *(const float2*)&w2eS[(ch2 * 8 + g) * LDP2 + kb];
            mma_tf32(acc2, fu(HA0.x), fu(HA1.x), fu(HA0.y), fu(HA1.y), fu(B.x), fu(B.y));
        }
        const int c0a = ch2 * 8 + 2 * tig;
        const float bb0 = b2S[c0a], bb1 = b2S[c0a + 1];
        float2 v0, v1;
        v0.x = fmaxf(acc2[0] + bb0, 0.f) + 0.001f;
        v0.y = fmaxf(acc2[1] + bb1, 0.f) + 0.001f;
        v1.x = fmaxf(acc2[2] + bb0, 0.f) + 0.001f;
        v1.y = fmaxf(acc2[3] + bb1, 0.f) + 0.001f;
        *(float2*)&attS[(rg2 * 16 + g) * 16 + c0a]     = v0;
        *(float2*)&attS[(rg2 * 16 + g + 8) * 16 + c0a] = v1;
    }
    __syncthreads();

    // ---- attractor: 8 thr/pixel (8 bins each), packed f32x2 pairwise ----
    unsigned long long atp[16];
    {
        const float4* ap = (const float4*)&attS[pxl * 16];
#pragma unroll
        for (int qq = 0; qq < 4; qq++) {
            float4 v = ap[qq];
            atp[4 * qq + 0] = pack2(v.x, v.x);
            atp[4 * qq + 1] = pack2(v.y, v.y);
            atp[4 * qq + 2] = pack2(v.z, v.z);
            atp[4 * qq + 3] = pack2(v.w, v.w);
        }
    }
    const unsigned long long ONE2  = pack2(1.f, 1.f);
    const unsigned long long ZERO2 = pack2(0.f, 0.f);
    const unsigned long long AL2   = pack2(ALPHAc, ALPHAc);

    float* arr_s = vS;   // V dead
    float* out1 = out + (long long)bI * NB * HW + rem;
#pragma unroll 1
    for (int m = 0; m < 4; m++) {
        const int ch0 = 8 * (hb * 4 + m) + q4;     // pair (ch0, ch0+4)
        const float* p0 = peS + ch0 * PESTR;       // pbS
        const float* p1 = p0 + 4 * PESTR;
        float bc0 = w00 * p0[o00] + w01 * p0[o01] + w10 * p0[o10] + w11 * p0[o11];
        float bc1 = w00 * p1[o00] + w01 * p1[o01] + w10 * p1[o10] + w11 * p1[o11];
        const unsigned long long negb = pack2(-bc0, -bc1);
        unsigned long long s2 = ZERO2;
#pragma unroll
        for (int i = 0; i < 16; i += 2) {
            unsigned long long dx0 = fma2(atp[i],     ONE2, negb);
            unsigned long long t0  = fma2(dx0, AL2, ZERO2);
            unsigned long long dn0 = fma2(t0, dx0, ONE2);
            unsigned long long dx1 = fma2(atp[i + 1], ONE2, negb);
            unsigned long long t1  = fma2(dx1, AL2, ZERO2);
            unsigned long long dn1 = fma2(t1, dx1, ONE2);
            unsigned long long num = fma2(dx0, dn1, ZERO2);
            num = fma2(dx1, dn0, num);
            unsigned long long dpr = fma2(dn0, dn1, ZERO2);
            float dl, dh;
            unpack2(dpr, dl, dh);
            unsigned long long rp = pack2(rcpa(dl), rcpa(dh));
            s2 = fma2(num, rp, s2);
        }
        float s0, s1;
        unpack2(s2, s0, s1);
        float bn0 = bc0 + s0 * (1.0f / 16.0f);
        float bn1 = bc1 + s1 * (1.0f / 16.0f);
        out1[(long long)ch0 * HW]       = bn0;
        out1[(long long)(ch0 + 4) * HW] = bn1;
        // staggered staging: +16*(ch>>5) so paired sort readers are conflict-free
        arr_s[ch0 * ARRSTR + 16 * (ch0 >> 5) + pxl]             = fmaf(bn0, 9.999f, 0.001f);
        arr_s[(ch0 + 4) * ARRSTR + 16 * ((ch0 + 4) >> 5) + pxl] = fmaf(bn1, 9.999f, 0.001f);
    }
    __syncthreads();

    // ---- sort phase: 2 threads/pixel, sign-encoded bitonic + shfl merge ----
    if (t < 256) {
        const int s = t >> 1, h = t & 1;       // pixel s, half h
        const int py2 = s >> 4, px2 = s & 15;
        const int rem2 = (tY + py2) * Wc + (tX + px2);
        const unsigned int sgn  = (unsigned int)h << 31;
        const unsigned int psgn = (unsigned int)(h ^ 1) << 31;

        float arr[32];
#pragma unroll
        for (int l = 0; l < 32; l++) {
            float v = arr_s[(32 * h + l) * ARRSTR + 16 * h + s];
            arr[l] = __int_as_float(__float_as_int(v) ^ sgn);   // encode: h=1 negated
        }
        // static ascending bitonic sort of 32 encoded values
#pragma unroll
        for (int k = 2; k <= 32; k <<= 1) {
#pragma unroll
            for (int j = k >> 1; j > 0; j >>= 1) {
#pragma unroll
                for (int i = 0; i < 32; i++) {
                    int l = i ^ j;
                    if (l > i) {
                        float a = arr[i], bv = arr[l];
                        float mn = fminf(a, bv), mx = fmaxf(a, bv);
                        bool up = ((i & k) == 0);
                        arr[i] = up ? mn : mx;
                        arr[l] = up ? mx : mn;
                    }
                }
            }
        }
        // cross-thread merge (k=64, j=32) on true values: h=0 keeps min, h=1 max
#pragma unroll
        for (int l = 0; l < 32; l++) {
            float pw = __shfl_xor_sync(0xffffffffu, arr[l], 1);
            float z  = __int_as_float(__float_as_int(arr[l]) ^ sgn);
            float zp = __int_as_float(__float_as_int(pw) ^ psgn);
            float mn = fminf(z, zp), mx = fmaxf(z, zp);
            arr[l] = h ? mx : mn;
        }
        // final static ascending merges j=16..1
#pragma unroll
        for (int j = 16; j > 0; j >>= 1) {
#pragma unroll
            for (int i = 0; i < 32; i++) {
                int l = i ^ j;
                if (l > i) {
                    float a = arr[i], bv = arr[l];
                    arr[i] = fminf(a, bv);
                    arr[l] = fmaxf(a, bv);
                }
            }
        }
        float* out2 = out + half_out + (long long)bI * NB * HW + rem2;
#pragma unroll
        for (int l = 0; l < 32; l++) {
            const int ch = 32 * h + l;
            out2[(long long)ch * HW] = fminf(fmaxf(arr[l], 0.001f), 10.0f);
        }
    }
}

extern "C" void kernel_launch(void* const* d_in, const int* in_sizes, int n_in,
                              void* d_out, int out_size) {
    const float* x  = (const float*)d_in[0];
    const float* pb = (const float*)d_in[1];
    const float* pe = (const float*)d_in[2];
    const float* w1 = (const float*)d_in[3];
    const float* b1 = (const float*)d_in[4];
    const float* w2 = (const float*)d_in[5];
    const float* b2 = (const float*)d_in[6];
    float* out = (float*)d_out;

    const long long half_out = (long long)out_size / 2;
    const int grid = 12 * 24 * 4;    // exact tile cover: 1152 CTAs

    cudaFuncSetAttribute(zoe_head_tile_kernel,
                         cudaFuncAttributeMaxDynamicSharedMemorySize, SMEM_BYTES);

    zoe_head_tile_kernel<<<grid, NTHR, SMEM_BYTES>>>(x, pb, pe, w1, b1, w2, b2, out,
                                                     half_out);
}

// round 17
// speedup vs baseline: 1.1000x; 1.1000x over previous
#include <cuda_runtime.h>
#include <cstdint>

// ZoeDepth metric depth head — fused, 2x(16x8) tiles per CTA, smem-staged
// bilinear, weights staged once, pe(tile1) staging overlapped with GEMM1(tile0).
// h tile lives in the dead V region so W1 survives both tiles.

namespace {
constexpr int Hc = 192, Wc = 192, SHc = 96, SWc = 96, Cc = 128, NB = 64, NA = 16;
constexpr int NTHR = 512;
constexpr int TH = 8;
constexpr float ALPHAc = 300.0f;
constexpr int LDP2 = 136;     // paired V/W row stride
constexpr int PESTR = 72;     // pe channel stride (6*10=60 used)
constexpr int PBSTR = 120;    // pb channel stride (6*18=108 used) — banks {0,24,16,8}
constexpr int ARRSTR = 136;   // sort staging stride

// smem layout (floats)
constexpr int OFF_PB  = 0;                      // 64*120  = 7680
constexpr int OFF_PE  = OFF_PB + 64 * PBSTR;    // 128*72  = 9216
constexpr int OFF_V   = OFF_PE + 128 * PESTR;   // 128*136 ; reused as h tile, then arr_s
constexpr int OFF_W1  = OFF_V  + 128 * LDP2;    // 128*136 (persists across both tiles)
constexpr int OFF_W2E = OFF_W1 + 128 * LDP2;    // 16*136
constexpr int OFF_B1S = OFF_W2E + 16 * LDP2;    // 128
constexpr int OFF_B2S = OFF_B1S + 128;          // 16
constexpr int OFF_ATT = OFF_B2S + 16;           // 128*16 (byte off 216128, 16B aligned)
constexpr int SMEM_FLOATS = OFF_ATT + 128 * 16; // 56080
constexpr int SMEM_BYTES  = SMEM_FLOATS * 4;    // 224320 B <= 227KB cap

__device__ __forceinline__ int pslot(int c) {
    return ((c >> 3) << 3) + ((c & 3) << 1) + ((c >> 2) & 1);
}
__device__ __forceinline__ float rna_tf32(float x) {
    float r; asm("cvt.rna.tf32.f32 %0, %1;" : "=f"(r) : "f"(x)); return r;
}
__device__ __forceinline__ float rcpa(float x) {
    float r; asm("rcp.approx.f32 %0, %1;" : "=f"(r) : "f"(x)); return r;
}
__device__ __forceinline__ unsigned long long pack2(float lo, float hi) {
    unsigned long long r;
    asm("mov.b64 %0, {%1, %2};" : "=l"(r) : "f"(lo), "f"(hi));
    return r;
}
__device__ __forceinline__ void unpack2(unsigned long long v, float& lo, float& hi) {
    asm("mov.b64 {%0, %1}, %2;" : "=f"(lo), "=f"(hi) : "l"(v));
}
__device__ __forceinline__ unsigned long long fma2(unsigned long long a,
                                                   unsigned long long b,
                                                   unsigned long long c) {
    unsigned long long d;
    asm("fma.rn.f32x2 %0, %1, %2, %3;" : "=l"(d) : "l"(a), "l"(b), "l"(c));
    return d;
}
__device__ __forceinline__ void mma_tf32(float* d,
                                         uint32_t a0, uint32_t a1, uint32_t a2, uint32_t a3,
                                         uint32_t b0, uint32_t b1) {
    asm volatile("mma.sync.aligned.m16n8k8.row.col.f32.tf32.tf32.f32 "
                 "{%0,%1,%2,%3}, {%4,%5,%6,%7}, {%8,%9}, {%0,%1,%2,%3};"
                 : "+f"(d[0]), "+f"(d[1]), "+f"(d[2]), "+f"(d[3])
                 : "r"(a0), "r"(a1), "r"(a2), "r"(a3), "r"(b0), "r"(b1));
}
__device__ __forceinline__ uint32_t fu(float x) { return __float_as_uint(x); }
} // namespace

__global__ __launch_bounds__(NTHR, 1)
void zoe_head_tile_kernel(const float* __restrict__ x,
                          const float* __restrict__ prev_bin,
                          const float* __restrict__ pe,
                          const float* __restrict__ w1,
                          const float* __restrict__ b1,
                          const float* __restrict__ w2,
                          const float* __restrict__ b2,
                          float* __restrict__ out,
                          long long half_out)
{
    extern __shared__ float smem[];
    float* pbS  = smem + OFF_PB;
    float* peS  = smem + OFF_PE;
    float* vS   = smem + OFF_V;      // V tile -> h tile -> sort staging
    float* w1S  = smem + OFF_W1;
    float* w2eS = smem + OFF_W2E;
    float* b1S  = smem + OFF_B1S;
    float* b2S  = smem + OFF_B2S;
    float* attS = smem + OFF_ATT;

    const int t = threadIdx.x;
    const int wid = t >> 5, lid = t & 31;
    const int g = lid >> 2, tig = lid & 3;
    const int HW = Hc * Wc, SHW = SHc * SWc;

    // ---- CTA = 32x8 pixel region ----
    const int bx = blockIdx.x;
    const int tX32 = (bx % 6) * 32;
    const int tY   = ((bx / 6) % 24) * TH;
    const int bI   = bx / 144;
    const float fscale = (float)(SHc - 1) / (float)(Hc - 1);
    const int ybase = (int)((float)tY * fscale);
    const int xb32  = (int)((float)tX32 * fscale);

    // ---- stage W1 / W2even / biases into paired tf32 layout (once) ----
    {
        const float4* w1v = (const float4*)w1;
#pragma unroll
        for (int i = 0; i < 4; i++) {
            int idx8 = t + i * NTHR;          // 0..2047
            int o = idx8 >> 4, g8 = idx8 & 15;
            float4 lo = w1v[o * 32 + g8 * 2];
            float4 hi = w1v[o * 32 + g8 * 2 + 1];
            float* dst = &w1S[o * LDP2 + g8 * 8];
            *(float2*)&dst[0] = make_float2(rna_tf32(lo.x), rna_tf32(hi.x));
            *(float2*)&dst[2] = make_float2(rna_tf32(lo.y), rna_tf32(hi.y));
            *(float2*)&dst[4] = make_float2(rna_tf32(lo.z), rna_tf32(hi.z));
            *(float2*)&dst[6] = make_float2(rna_tf32(lo.w), rna_tf32(hi.w));
        }
        if (t < 256) {
            int o = t >> 4, g8 = t & 15;
            const float4* w2v = (const float4*)w2;
            float4 lo = w2v[(2 * o) * 32 + g8 * 2];
            float4 hi = w2v[(2 * o) * 32 + g8 * 2 + 1];
            float* dst = &w2eS[o * LDP2 + g8 * 8];
            *(float2*)&dst[0] = make_float2(rna_tf32(lo.x), rna_tf32(hi.x));
            *(float2*)&dst[2] = make_float2(rna_tf32(lo.y), rna_tf32(hi.y));
            *(float2*)&dst[4] = make_float2(rna_tf32(lo.z), rna_tf32(hi.z));
            *(float2*)&dst[6] = make_float2(rna_tf32(lo.w), rna_tf32(hi.w));
        }
        if (t < Cc) b1S[t] = b1[t];
        if (t < NA) b2S[t] = b2[2 * t];
    }

    // ---- stage pe (tile 0): 128 ch x 6 x 10 ----
    {
        const float* peb = pe + (long long)bI * Cc * SHW;
#pragma unroll
        for (int i = 0; i < 16; i++) {
            int idx = t + i * NTHR;            // 0..8191
            int c = idx >> 6, r = idx & 63;
            if (r < 60) {
                int ly = r / 10, lx = r - ly * 10;
                int sy = min(ybase + ly, SHc - 1);
                int sx = min(xb32 + lx, SWc - 1);
                peS[c * PESTR + r] = __ldg(peb + (long long)c * SHW + sy * SWc + sx);
            }
        }
    }
    // ---- stage pb (whole 32-wide span): 64 ch x 6 x 18 ----
    {
        const float* pbb = prev_bin + (long long)bI * NB * SHW;
#pragma unroll
        for (int i = 0; i < 16; i++) {
            int idx = t + i * NTHR;            // 0..8191
            int c = idx >> 7, r = idx & 127;
            if (r < 108) {
                int ly = r / 18, lx = r - ly * 18;
                int sy = min(ybase + ly, SHc - 1);
                int sx = min(xb32 + lx, SWc - 1);
                pbS[c * PBSTR + r] = __ldg(pbb + (long long)c * SHW + sy * SWc + sx);
            }
        }
    }
    __syncthreads();

    const int pxl = t >> 2, q4 = t & 3;
    const int py = pxl >> 4, px = pxl & 15;
    const int rg = wid >> 2, cgw = wid & 3;
    const int r0 = rg * 32, c0 = cgw * 32;

#pragma unroll 1
    for (int hh = 0; hh < 2; hh++) {
        const int tXh = tX32 + 16 * hh;
        const int xbh = (int)((float)tXh * fscale);
        // ---- per-pixel bilinear coords for this tile ----
        const int yy = tY + py, xx = tXh + px;
        const int rem = yy * Wc + xx;
        const float fy = yy * fscale, fx = xx * fscale;
        const int y0 = (int)fy, x0 = (int)fx;
        const int y1 = min(y0 + 1, SHc - 1), x1 = min(x0 + 1, SWc - 1);
        const float wy = fy - (float)y0, wx = fx - (float)x0;
        const float w00 = (1.f - wy) * (1.f - wx), w01 = (1.f - wy) * wx;
        const float w10 = wy * (1.f - wx),          w11 = wy * wx;
        const int dy0 = y0 - ybase, dy1 = y1 - ybase;
        const int o00 = dy0 * 10 + (x0 - xbh), o01 = dy0 * 10 + (x1 - xbh);
        const int o10 = dy1 * 10 + (x0 - xbh), o11 = dy1 * 10 + (x1 - xbh);

        // ---- build V tile: v = x + bilinear(peS), rna->tf32, paired ----
        {
            const float* xb = x + (long long)bI * Cc * HW + rem;
            float* vrow = vS + pxl * LDP2;
#pragma unroll
            for (int m = 0; m < 16; m++) {
                const int cc0 = 8 * m + q4;
                const float* p0 = peS + cc0 * PESTR;
                const float* p1 = p0 + 4 * PESTR;
                float v0 = w00 * p0[o00] + w01 * p0[o01] + w10 * p0[o10] + w11 * p0[o11]
                         + __ldg(xb + (long long)cc0 * HW);
                float v1 = w00 * p1[o00] + w01 * p1[o01] + w10 * p1[o10] + w11 * p1[o11]
                         + __ldg(xb + (long long)(cc0 + 4) * HW);
                *(float2*)&vrow[m * 8 + q4 * 2] = make_float2(rna_tf32(v0), rna_tf32(v1));
            }
        }
        __syncthreads();   // V ready; peS free for re-staging

        // ---- GEMM1: 16 warps = 4x4, warp tile 32x32 ----
        float acc[2][4][4];
#pragma unroll
        for (int rt = 0; rt < 2; rt++)
#pragma unroll
            for (int ct = 0; ct < 4; ct++)
#pragma unroll
                for (int qq = 0; qq < 4; qq++) acc[rt][ct][qq] = 0.f;

#pragma unroll 4
        for (int k = 0; k < 16; k++) {
            const int kb = k * 8 + 2 * tig;
            float2 A0 = *(const float2*)&vS[(r0 + g) * LDP2 + kb];
            float2 A1 = *(const float2*)&vS[(r0 + g + 8) * LDP2 + kb];
            float2 A2 = *(const float2*)&vS[(r0 + 16 + g) * LDP2 + kb];
            float2 A3 = *(const float2*)&vS[(r0 + 24 + g) * LDP2 + kb];
#pragma unroll
            for (int ct = 0; ct < 4; ct++) {
                float2 B = *(const float2*)&w1S[(c0 + ct * 8 + g) * LDP2 + kb];
                mma_tf32(acc[0][ct], fu(A0.x), fu(A1.x), fu(A0.y), fu(A1.y), fu(B.x), fu(B.y));
                mma_tf32(acc[1][ct], fu(A2.x), fu(A3.x), fu(A2.y), fu(A3.y), fu(B.x), fu(B.y));
            }
        }

        // ---- overlap: stage pe for tile 1 during tile 0's GEMM1 ----
        if (hh == 0) {
            const int xb1 = (int)((float)(tX32 + 16) * fscale);
            const float* peb = pe + (long long)bI * Cc * SHW;
#pragma unroll
            for (int i = 0; i < 16; i++) {
                int idx = t + i * NTHR;
                int c = idx >> 6, r = idx & 63;
                if (r < 60) {
                    int ly = r / 10, lx = r - ly * 10;
                    int sy = min(ybase + ly, SHc - 1);
                    int sx = min(xb1 + lx, SWc - 1);
                    peS[c * PESTR + r] = __ldg(peb + (long long)c * SHW + sy * SWc + sx);
                }
            }
        }
        __syncthreads();   // GEMM1 done -> vS overwritable with h

        // ---- epilogue 1: h = rna(relu(D1+b1)) -> h tile in vS (V dead) ----
        {
            float* hS = vS;
#pragma unroll
            for (int rt = 0; rt < 2; rt++) {
                const int ra = (r0 + rt * 16 + g) * LDP2;
                const int rb = ra + 8 * LDP2;
#pragma unroll
                for (int ct = 0; ct < 4; ct++) {
                    const int c = c0 + ct * 8 + 2 * tig;
                    const float bb0 = b1S[c], bb1 = b1S[c + 1];
                    const int s0 = pslot(c), s1 = pslot(c + 1);
                    hS[ra + s0] = rna_tf32(fmaxf(acc[rt][ct][0] + bb0, 0.f));
                    hS[ra + s1] = rna_tf32(fmaxf(acc[rt][ct][1] + bb1, 0.f));
                    hS[rb + s0] = rna_tf32(fmaxf(acc[rt][ct][2] + bb0, 0.f));
                    hS[rb + s1] = rna_tf32(fmaxf(acc[rt][ct][3] + bb1, 0.f));
                }
            }
        }
        __syncthreads();

        // ---- GEMM2: warp = (row-group of 16, n-tile); att[16][8] ----
        {
            const float* hS = vS;
            const int rg2 = wid >> 1, ch2 = wid & 1;
            const int rA0 = (rg2 * 16 + g) * LDP2;
            const int rA1 = rA0 + 8 * LDP2;
            float acc2[4] = {0.f, 0.f, 0.f, 0.f};
#pragma unroll
            for (int k = 0; k < 16; k++) {
                const int kb = k * 8 + 2 * tig;
                float2 HA0 = *(const float2*)&hS[rA0 + kb];
                float2 HA1 = *(const float2*)&hS[rA1 + kb];
                float2 B = *(const float2*)&w2eS[(ch2 * 8 + g) * LDP2 + kb];
                mma_tf32(acc2, fu(HA0.x), fu(HA1.x), fu(HA0.y), fu(HA1.y), fu(B.x), fu(B.y));
            }
            const int c0a = ch2 * 8 + 2 * tig;
            const float bb0 = b2S[c0a], bb1 = b2S[c0a + 1];
            float2 v0, v1;
            v0.x = fmaxf(acc2[0] + bb0, 0.f) + 0.001f;
            v0.y = fmaxf(acc2[1] + bb1, 0.f) + 0.001f;
            v1.x = fmaxf(acc2[2] + bb0, 0.f) + 0.001f;
            v1.y = fmaxf(acc2[3] + bb1, 0.f) + 0.001f;
            *(float2*)&attS[(rg2 * 16 + g) * 16 + c0a]     = v0;
            *(float2*)&attS[(rg2 * 16 + g + 8) * 16 + c0a] = v1;
        }
        __syncthreads();

        // ---- attractor: packed f32x2 pairwise; bc from pbS (stride 120) ----
        unsigned long long atp[16];
        {
            const float4* ap = (const float4*)&attS[pxl * 16];
#pragma unroll
            for (int qq = 0; qq < 4; qq++) {
                float4 v = ap[qq];
                atp[4 * qq + 0] = pack2(v.x, v.x);
                atp[4 * qq + 1] = pack2(v.y, v.y);
                atp[4 * qq + 2] = pack2(v.z, v.z);
                atp[4 * qq + 3] = pack2(v.w, v.w);
            }
        }
        const unsigned long long ONE2  = pack2(1.f, 1.f);
        const unsigned long long ZERO2 = pack2(0.f, 0.f);
        const unsigned long long AL2   = pack2(ALPHAc, ALPHAc);

        const int p00 = dy0 * 18 + (x0 - xb32), p01 = dy0 * 18 + (x1 - xb32);
        const int p10 = dy1 * 18 + (x0 - xb32), p11 = dy1 * 18 + (x1 - xb32);

        float* arr_s = vS;   // h dead after GEMM2
        float* out1 = out + (long long)bI * NB * HW + rem;
#pragma unroll 1
        for (int m = 0; m < 8; m++) {
            const int ch0 = 8 * m + q4;            // pair (ch0, ch0+4)
            const float* bp0 = pbS + ch0 * PBSTR;
            const float* bp1 = bp0 + 4 * PBSTR;
            float bc0 = w00 * bp0[p00] + w01 * bp0[p01] + w10 * bp0[p10] + w11 * bp0[p11];
            float bc1 = w00 * bp1[p00] + w01 * bp1[p01] + w10 * bp1[p10] + w11 * bp1[p11];
            const unsigned long long negb = pack2(-bc0, -bc1);
            unsigned long long s2 = ZERO2;
#pragma unroll
            for (int i = 0; i < 16; i += 2) {
                unsigned long long dx0 = fma2(atp[i],     ONE2, negb);
                unsigned long long t0  = fma2(dx0, AL2, ZERO2);
                unsigned long long dn0 = fma2(t0, dx0, ONE2);
                unsigned long long dx1 = fma2(atp[i + 1], ONE2, negb);
                unsigned long long t1  = fma2(dx1, AL2, ZERO2);
                unsigned long long dn1 = fma2(t1, dx1, ONE2);
                unsigned long long num = fma2(dx0, dn1, ZERO2);
                num = fma2(dx1, dn0, num);
                unsigned long long dpr = fma2(dn0, dn1, ZERO2);
                float dl, dh;
                unpack2(dpr, dl, dh);
                unsigned long long rp = pack2(rcpa(dl), rcpa(dh));
                s2 = fma2(num, rp, s2);
            }
            float s0, s1;
            unpack2(s2, s0, s1);
            float bn0 = bc0 + s0 * (1.0f / 16.0f);
            float bn1 = bc1 + s1 * (1.0f / 16.0f);
            out1[(long long)ch0 * HW]       = bn0;
            out1[(long long)(ch0 + 4) * HW] = bn1;
            arr_s[ch0 * ARRSTR + pxl]       = fmaf(bn0, 9.999f, 0.001f);
            arr_s[(ch0 + 4) * ARRSTR + pxl] = fmaf(bn1, 9.999f, 0.001f);
        }
        __syncthreads();

        // ---- sort: threads 0..127 each sort one pixel (bitonic-64) ----
        if (t < 128) {
            const int py2 = t >> 4, px2 = t & 15;
            const int rem2 = (tY + py2) * Wc + (tXh + px2);
            float arr[64];
#pragma unroll
            for (int ch = 0; ch < 64; ch++) arr[ch] = arr_s[ch * ARRSTR + t];
#pragma unroll
            for (int k = 2; k <= 64; k <<= 1) {
#pragma unroll
                for (int j = k >> 1; j > 0; j >>= 1) {
#pragma unroll
                    for (int i = 0; i < 64; i++) {
                        int l = i ^ j;
                        if (l > i) {
                            float a = arr[i], bv = arr[l];
                            float mn = fminf(a, bv), mx = fmaxf(a, bv);
                            bool up = ((i & k) == 0);
                            arr[i] = up ? mn : mx;
                            arr[l] = up ? mx : mn;
                        }
                    }
                }
            }
            float* out2 = out + half_out + (long long)bI * NB * HW + rem2;
#pragma unroll
            for (int ch = 0; ch < 64; ch++)
                out2[(long long)ch * HW] = fminf(fmaxf(arr[ch], 0.001f), 10.0f);
        }
        __syncthreads();   // protect vS (arr_s) before next tile's V build
    }
}

extern "C" void kernel_launch(void* const* d_in, const int* in_sizes, int n_in,
                              void* d_out, int out_size) {
    const float* x  = (const float*)d_in[0];
    const float* pb = (const float*)d_in[1];
    const float* pe = (const float*)d_in[2];
    const float* w1 = (const float*)d_in[3];
    const float* b1 = (const float*)d_in[4];
    const float* w2 = (const float*)d_in[5];
    const float* b2 = (const float*)d_in[6];
    float* out = (float*)d_out;

    const long long half_out = (long long)out_size / 2;
    const int grid = 6 * 24 * 4;     // 576 CTAs, each 32x8 px (exact cover)

    cudaFuncSetAttribute(zoe_head_tile_kernel,
                         cudaFuncAttributeMaxDynamicSharedMemorySize, SMEM_BYTES);

    zoe_head_tile_kernel<<<grid, NTHR, SMEM_BYTES>>>(x, pb, pe, w1, b1, w2, b2, out,
                                                     half_out);
}